// round 14
// baseline (speedup 1.0000x reference)
#include <cuda_runtime.h>
#include <cstdint>

// ---------------------------------------------------------------------------
// TreeDecoder on GB300 — round 14: 3 CTAs/SM occupancy experiment.
//  * main: As smem tile removed (a-operands = warp-uniform LDG.64 pairs from
//    tree3); smem 73728B (C1 12288f + Wb 2x3072f) -> 3 CTAs/SM, 24 warps.
//  * GEMM1: 16 stages K=8 (round-8 fill); GEMM2: 8 stages K=16 (round-10).
//  * launch_bounds(256,3); Fcomb stream uses cp.async.cg (spare L1D).
// ---------------------------------------------------------------------------

#define NSPLIT 10
#define N_PRE    184            // 40 Fcomb + 128 Q2 + 16 Q01
#define N_MAIN   1024
#define N_BLOCKS (N_PRE + N_MAIN)
#define N_RED    64             // main blocks 184..247 also reduce

typedef unsigned long long ull;

__device__ __forceinline__ ull dup2(float x) {
    ull r; unsigned u = __float_as_uint(x);
    asm("mov.b64 %0, {%1, %1};" : "=l"(r) : "r"(u));
    return r;
}
__device__ __forceinline__ void fma2(ull& d, ull a, ull b) {
    asm("fma.rn.f32x2 %0, %1, %2, %0;" : "+l"(d) : "l"(a), "l"(b));
}
__device__ __forceinline__ float lo32(ull v) { return __uint_as_float((unsigned)v); }
__device__ __forceinline__ float hi32(ull v) { return __uint_as_float((unsigned)(v >> 32)); }
__device__ __forceinline__ unsigned smem_u32(const void* p) {
    unsigned a;
    asm("{ .reg .u64 t; cvta.to.shared.u64 t, %1; cvt.u32.u64 %0, t; }" : "=r"(a) : "l"(p));
    return a;
}
__device__ __forceinline__ void cp16_cg(unsigned s, const void* g) {
    asm volatile("cp.async.cg.shared.global [%0], [%1], 16;" :: "r"(s), "l"(g));
}
__device__ __forceinline__ void cp16_ca(unsigned s, const void* g) {
    asm volatile("cp.async.ca.shared.global [%0], [%1], 16;" :: "r"(s), "l"(g));
}
#define CP_COMMIT()  asm volatile("cp.async.commit_group;")
#define CP_WAIT0()   asm volatile("cp.async.wait_group 0;")

// Device scratch (zero-init counters; last block re-zeroes per launch)
__device__ float g_Fcomb[16384];
__device__ float g_Fbias[128];
__device__ float g_Fpart[NSPLIT * 16384];
__device__ float g_Fbpart[NSPLIT * 128];
__device__ float g_A2[32 * 128 * 128];
__device__ float g_Q01[32 * 16 * 128];
__device__ int   g_cnt_f;      // Fcomb partial blocks done (target 40)
__device__ int   g_cnt_r;      // reduce slices done       (target 64)
__device__ int   g_cnt_pre;    // Q2 + Q01 blocks done     (target 144)
__device__ int   g_cnt_done;   // all blocks done          (target 1208)

__device__ __forceinline__ void block_signal(int* cnt) {
    __threadfence();
    __syncthreads();
    if (threadIdx.x == 0) atomicAdd(cnt, 1);
}
__device__ __forceinline__ void block_wait(int* cnt, int target) {
    if (threadIdx.x == 0) {
        while (atomicAdd(cnt, 0) < target) __nanosleep(128);
        __threadfence();
    }
    __syncthreads();
}

// ---------------------------------------------------------------------------
__global__ __launch_bounds__(256, 3)
void fused_kernel(const float* __restrict__ tree0,
                  const float* __restrict__ tree1,
                  const float* __restrict__ tree2,
                  const float* __restrict__ tree3,
                  const float* __restrict__ Uw0, const float* __restrict__ Ub0,
                  const float* __restrict__ Uw1, const float* __restrict__ Ub1,
                  const float* __restrict__ Uw2, const float* __restrict__ Ub2,
                  const float* __restrict__ Uw3, const float* __restrict__ Ub3,
                  const float* __restrict__ W_up,
                  const float* __restrict__ Fw0, const float* __restrict__ Fb0,
                  const float* __restrict__ Fw1, const float* __restrict__ Fb1,
                  const float* __restrict__ b_bias,
                  float* __restrict__ out) {
    extern __shared__ float sh[];
    const int tid = threadIdx.x;
    const int bx  = blockIdx.x;
    const int ty  = tid >> 5;
    const int tx  = tid & 31;

    if (bx < 40) {
        // ================= Fcomb split-K partial =================
        float* As = sh;          // [32][128]
        float* Bs = sh + 4096;   // [32][128]
        const int s  = bx >> 2;
        const int rt = bx & 3;

        for (int i4 = tid; i4 < 1024; i4 += 256) {
            int r = i4 >> 5, k4 = (i4 & 31) << 2;
            *(float4*)&As[r * 128 + k4] =
                *(const float4*)&Fw0[(rt * 32 + r) * 1280 + s * 128 + k4];
        }

        float acc[4][4] = {};
        float bacc = 0.f;

        for (int kb = 0; kb < 128; kb += 32) {
            __syncthreads();
            for (int i4 = tid; i4 < 1024; i4 += 256) {
                int j = i4 >> 5, o4 = (i4 & 31) << 2;
                *(float4*)&Bs[j * 128 + o4] =
                    *(const float4*)&Fw1[(s * 128 + kb + j) * 128 + o4];
            }
            __syncthreads();
            #pragma unroll 8
            for (int j = 0; j < 32; ++j) {
                float w[4];
                #pragma unroll
                for (int c = 0; c < 4; ++c) w[c] = Bs[j * 128 + tx + 32 * c];
                #pragma unroll
                for (int r = 0; r < 4; ++r) {
                    float a = As[(ty * 4 + r) * 128 + kb + j];
                    #pragma unroll
                    for (int c = 0; c < 4; ++c) acc[r][c] = fmaf(a, w[c], acc[r][c]);
                }
            }
            if (rt == 0 && tid < 128) {
                #pragma unroll 8
                for (int j = 0; j < 32; ++j)
                    bacc = fmaf(Fb0[s * 128 + kb + j], Bs[j * 128 + tid], bacc);
            }
        }

        #pragma unroll
        for (int r = 0; r < 4; ++r)
            #pragma unroll
            for (int c = 0; c < 4; ++c)
                g_Fpart[s * 16384 + (rt * 32 + ty * 4 + r) * 128 + tx + 32 * c] = acc[r][c];
        if (rt == 0 && tid < 128) g_Fbpart[s * 128 + tid] = bacc;

        block_signal(&g_cnt_f);

    } else if (bx < 168) {
        // ================= Q2 GEMM =================
        float* x2s = sh;          // [32][128]
        float* Bs  = sh + 4096;   // [32][128]
        const int bid = bx - 40;
        const int r0  = bid * 32;

        for (int i4 = tid; i4 < 1024; i4 += 256) {
            int lr = i4 >> 5, k4 = (i4 & 31) << 2;
            *(float4*)&x2s[lr * 128 + k4] =
                *(const float4*)&tree2[(r0 + lr) * 128 + k4];
        }

        float acc[4][4] = {};
        for (int kb = 0; kb < 128; kb += 32) {
            __syncthreads();
            for (int i4 = tid; i4 < 1024; i4 += 256) {
                int j = i4 >> 5, o4 = (i4 & 31) << 2;
                *(float4*)&Bs[j * 128 + o4] =
                    *(const float4*)&Uw2[(kb + j) * 128 + o4];
            }
            __syncthreads();
            #pragma unroll 8
            for (int j = 0; j < 32; ++j) {
                float w[4];
                #pragma unroll
                for (int c = 0; c < 4; ++c) w[c] = Bs[j * 128 + tx + 32 * c];
                #pragma unroll
                for (int r = 0; r < 4; ++r) {
                    float a = x2s[(ty * 4 + r) * 128 + kb + j];
                    #pragma unroll
                    for (int c = 0; c < 4; ++c) acc[r][c] = fmaf(a, w[c], acc[r][c]);
                }
            }
        }
        #pragma unroll
        for (int r = 0; r < 4; ++r)
            #pragma unroll
            for (int c = 0; c < 4; ++c)
                g_A2[(r0 + ty * 4 + r) * 128 + tx + 32 * c] = acc[r][c];

        block_signal(&g_cnt_pre);

    } else if (bx < N_PRE) {
        // ================= Q01: 32 flat (b,j1) rows =================
        float* t1s   = sh;            // [32][32]
        float* w1s   = sh + 1024;     // [32][128]
        float* w0s   = sh + 5120;     // [32][128]
        float* t0s   = sh + 9216;     // [2][32]
        float* q0buf = sh + 9280;     // [2][128]
        const int q  = bx - 168;
        const int g0 = q * 32;

        float acc[4][4] = {};
        float q0a = 0.f;
        const int q0row = tid >> 7;
        const int q0col = tid & 127;

        for (int kb = 0; kb < 128; kb += 32) {
            __syncthreads();
            {
                int row = tid >> 3, k4 = (tid & 7) << 2;
                *(float4*)&t1s[row * 32 + k4] =
                    *(const float4*)&tree1[(g0 + row) * 128 + kb + k4];
            }
            for (int i4 = tid; i4 < 1024; i4 += 256) {
                int j = i4 >> 5, o4 = (i4 & 31) << 2;
                *(float4*)&w1s[j * 128 + o4] =
                    *(const float4*)&Uw1[(kb + j) * 128 + o4];
                *(float4*)&w0s[j * 128 + o4] =
                    *(const float4*)&Uw0[(kb + j) * 128 + o4];
            }
            if (tid < 16) {
                int row = tid >> 3, k4 = (tid & 7) << 2;
                *(float4*)&t0s[row * 32 + k4] =
                    *(const float4*)&tree0[(q * 2 + row) * 128 + kb + k4];
            }
            __syncthreads();
            #pragma unroll 8
            for (int j = 0; j < 32; ++j) {
                float w[4];
                #pragma unroll
                for (int c = 0; c < 4; ++c) w[c] = w1s[j * 128 + tx + 32 * c];
                #pragma unroll
                for (int r = 0; r < 4; ++r) {
                    float a = t1s[(ty * 4 + r) * 32 + j];
                    #pragma unroll
                    for (int c = 0; c < 4; ++c) acc[r][c] = fmaf(a, w[c], acc[r][c]);
                }
            }
            #pragma unroll 8
            for (int j = 0; j < 32; ++j)
                q0a = fmaf(t0s[q0row * 32 + j], w0s[j * 128 + q0col], q0a);
        }
        __syncthreads();
        q0buf[tid] = q0a;
        __syncthreads();

        #pragma unroll
        for (int r = 0; r < 4; ++r) {
            int row = ty * 4 + r;
            int bl  = row >> 4;
            #pragma unroll
            for (int c = 0; c < 4; ++c) {
                int col = tx + 32 * c;
                g_Q01[(g0 + row) * 128 + col] =
                    acc[r][c] + q0buf[bl * 128 + col]
                    + Ub0[col] + Ub1[col] + Ub2[col];
            }
        }

        block_signal(&g_cnt_pre);

    } else {
        // ================= main: per-node fused GEMM1+GEMM2 =================
        // smem: C1 [32][384] | Wb [2][3072]  = 18432 floats = 73728 B
        float* C1 = sh;               // 12288 floats
        float* Wb = sh + 12288;       // 6144 floats (2 x 3072)

        const int n = bx - N_PRE;
        const unsigned wb_u32 = smem_u32(Wb);

        // GEMM1 fill: 3 x 16B per thread per stage over [8 rows][96 float4]
        const char* g1src[3];
        int         g1step[3];
        unsigned    g1soff[3];
        #pragma unroll
        for (int q = 0; q < 3; ++q) {
            int g = tid + 256 * q;
            int kk = g / 96, c4 = g - kk * 96;
            if (c4 < 64) {
                g1src[q]  = (const char*)(W_up + ((size_t)n * 128 + kk) * 256 + c4 * 4);
                g1step[q] = 8 * 256 * 4;
            } else {
                g1src[q]  = (const char*)(Uw3 + kk * 128 + (c4 - 64) * 4);
                g1step[q] = 8 * 128 * 4;
            }
            g1soff[q] = (unsigned)(kk * 384 + c4 * 4) * 4;
        }

        // Prologue: stage 0 into buffer 0
        #pragma unroll
        for (int q = 0; q < 3; ++q) cp16_cg(wb_u32 + g1soff[q], g1src[q]);
        CP_COMMIT();

        const int tn = tid & 31;
        const int tm = tid >> 5;

        // a-operand row pointers (warp-uniform; LDG.64 broadcast in the loop)
        const float* t3p[4];
        #pragma unroll
        for (int r = 0; r < 4; ++r)
            t3p[r] = tree3 + ((size_t)(tm * 4 + r) * 1024 + n) * 128;

        ull acc[4][6] = {};

        // ---- GEMM1: 16 stages of K=8, double-buffered, a from global ----
        for (int it = 0; it < 16; ++it) {
            CP_WAIT0();
            __syncthreads();
            if (it < 15) {
                unsigned dst = wb_u32 + (unsigned)(((it + 1) & 1) * 3072 * 4);
                #pragma unroll
                for (int q = 0; q < 3; ++q) {
                    g1src[q] += g1step[q];
                    cp16_cg(dst + g1soff[q], g1src[q]);
                }
                CP_COMMIT();
            }
            const float* buf = Wb + (it & 1) * 3072;
            const int k0 = it * 8;
            #pragma unroll
            for (int kk = 0; kk < 8; kk += 2) {
                float2 av[4];
                #pragma unroll
                for (int r = 0; r < 4; ++r)
                    av[r] = *(const float2*)&t3p[r][k0 + kk];
                {   // k = k0+kk
                    ull w[6];
                    #pragma unroll
                    for (int j = 0; j < 6; ++j)
                        w[j] = *(const ull*)&buf[kk * 384 + tn * 2 + 64 * j];
                    #pragma unroll
                    for (int r = 0; r < 4; ++r) {
                        ull ad = dup2(av[r].x);
                        #pragma unroll
                        for (int j = 0; j < 6; ++j) fma2(acc[r][j], ad, w[j]);
                    }
                }
                {   // k = k0+kk+1
                    ull w[6];
                    #pragma unroll
                    for (int j = 0; j < 6; ++j)
                        w[j] = *(const ull*)&buf[(kk + 1) * 384 + tn * 2 + 64 * j];
                    #pragma unroll
                    for (int r = 0; r < 4; ++r) {
                        ull ad = dup2(av[r].y);
                        #pragma unroll
                        for (int j = 0; j < 6; ++j) fma2(acc[r][j], ad, w[j]);
                    }
                }
            }
        }

        // Store C1; publish + ensure GEMM1 buffer reads complete
        #pragma unroll
        for (int r = 0; r < 4; ++r)
            #pragma unroll
            for (int j = 0; j < 6; ++j)
                *(ull*)&C1[(tm * 4 + r) * 384 + tn * 2 + 64 * j] = acc[r][j];
        __syncthreads();

        // ---- In-kernel Fcomb reduce (blocks 184..247) ----
        if (n < N_RED) {
            block_wait(&g_cnt_f, 40);
            int idx = n * 256 + tid;           // one element each, fixed order
            float a = 0.f;
            #pragma unroll
            for (int s = 0; s < NSPLIT; ++s) a += g_Fpart[s * 16384 + idx];
            g_Fcomb[idx] = a;
            if (n == 0 && tid < 128) {
                float b = Fb1[tid];
                #pragma unroll
                for (int s = 0; s < NSPLIT; ++s) b += g_Fbpart[s * 128 + tid];
                g_Fbias[tid] = b;
            }
            block_signal(&g_cnt_r);
        }

        // All main blocks: wait for the reduced Fcomb
        block_wait(&g_cnt_r, N_RED);

        // GEMM2 prologue: Fcomb stage 0 (2048 floats = K=16) into buffer 0
        cp16_cg(wb_u32 + (unsigned)tid * 16, (const char*)g_Fcomb + tid * 16);
        cp16_cg(wb_u32 + (unsigned)(tid + 256) * 16,
                (const char*)g_Fcomb + (tid + 256) * 16);
        CP_COMMIT();

        ull acc2[8][2] = {};

        // ---- GEMM2: 8 stages of K=16, double-buffered ----
        for (int it = 0; it < 8; ++it) {
            CP_WAIT0();
            __syncthreads();
            if (it < 7) {
                unsigned dst = wb_u32 + (unsigned)(((it + 1) & 1) * 3072 * 4);
                const char* src = (const char*)(g_Fcomb + (it + 1) * 2048);
                cp16_cg(dst + (unsigned)tid * 16, src + tid * 16);
                cp16_cg(dst + (unsigned)(tid + 256) * 16, src + (tid + 256) * 16);
                CP_COMMIT();
            }
            const float* buf = Wb + (it & 1) * 3072;
            const int k0 = it * 16;
            #pragma unroll
            for (int kk = 0; kk < 16; ++kk) {
                ull f0 = *(const ull*)&buf[kk * 128 + tx * 2];
                ull f1 = *(const ull*)&buf[kk * 128 + tx * 2 + 64];
                #pragma unroll
                for (int r = 0; r < 8; ++r) {
                    int row = ty * 8 + r;
                    ull ad = dup2(C1[(row >> 1) * 384 + (row & 1) * 128 + k0 + kk]);
                    fma2(acc2[r][0], ad, f0);
                    fma2(acc2[r][1], ad, f1);
                }
            }
        }

        // Wait for A2/Q01 producers before the epilogue gather
        block_wait(&g_cnt_pre, 144);

        // ---- Epilogue ----
        const int j2 = n >> 3;
        const int j1 = n >> 6;
        float2 ub[2], fb[2];
        #pragma unroll
        for (int c = 0; c < 2; ++c) {
            int col = tx * 2 + 64 * c;
            ub[c] = *(const float2*)&Ub3[col];
            fb[c] = *(const float2*)&g_Fbias[col];
        }
        #pragma unroll
        for (int r = 0; r < 8; ++r) {
            int row = ty * 8 + r;
            int bb  = row >> 1;
            int d   = row & 1;
            int gr  = 2 * n + d;
            #pragma unroll
            for (int c = 0; c < 2; ++c) {
                int col = tx * 2 + 64 * c;
                float2 t3  = *(const float2*)&C1[bb * 384 + 256 + col];
                float2 a2v = *(const float2*)&g_A2[(bb * 128 + j2) * 128 + col];
                float2 q01 = *(const float2*)&g_Q01[(bb * 16 + j1) * 128 + col];
                float2 bbv = *(const float2*)&b_bias[gr * 128 + col];
                float vx = lo32(acc2[r][c]) + t3.x + ub[c].x + a2v.x + q01.x + fb[c].x + bbv.x;
                float vy = hi32(acc2[r][c]) + t3.y + ub[c].y + a2v.y + q01.y + fb[c].y + bbv.y;
                float2 o;
                o.x = (vx >= 0.f) ? vx : 0.2f * vx;
                o.y = (vy >= 0.f) ? vy : 0.2f * vy;
                *(float2*)&out[((size_t)bb * 2048 + gr) * 128 + col] = o;
            }
        }
    }

    // ---- Per-launch counter cleanup: last block resets everything ----
    __syncthreads();
    if (tid == 0) {
        __threadfence();
        int d = atomicAdd(&g_cnt_done, 1);
        if (d == N_BLOCKS - 1) {
            g_cnt_f = 0; g_cnt_r = 0; g_cnt_pre = 0;
            __threadfence();
            g_cnt_done = 0;
        }
    }
}

// ---------------------------------------------------------------------------
extern "C" void kernel_launch(void* const* d_in, const int* in_sizes, int n_in,
                              void* d_out, int out_size) {
    const float* tree0  = (const float*)d_in[0];
    const float* tree1  = (const float*)d_in[1];
    const float* tree2  = (const float*)d_in[2];
    const float* tree3  = (const float*)d_in[3];
    const float* Uw0    = (const float*)d_in[4];
    const float* Ub0    = (const float*)d_in[5];
    const float* Uw1    = (const float*)d_in[6];
    const float* Ub1    = (const float*)d_in[7];
    const float* Uw2    = (const float*)d_in[8];
    const float* Ub2    = (const float*)d_in[9];
    const float* Uw3    = (const float*)d_in[10];
    const float* Ub3    = (const float*)d_in[11];
    const float* W_up   = (const float*)d_in[12];
    const float* Fw0    = (const float*)d_in[13];
    const float* Fb0    = (const float*)d_in[14];
    const float* Fw1    = (const float*)d_in[15];
    const float* Fb1    = (const float*)d_in[16];
    const float* b_bias = (const float*)d_in[17];
    float* out = (float*)d_out;

    cudaFuncSetAttribute(fused_kernel,
                         cudaFuncAttributeMaxDynamicSharedMemorySize, 73728);

    fused_kernel<<<N_BLOCKS, 256, 73728>>>(
        tree0, tree1, tree2, tree3,
        Uw0, Ub0, Uw1, Ub1, Uw2, Ub2, Uw3, Ub3,
        W_up, Fw0, Fb0, Fw1, Fb1, b_bias, out);
}

// round 17
// speedup vs baseline: 1.3198x; 1.3198x over previous
#include <cuda_runtime.h>
#include <cuda_bf16.h>
#include <cstdint>

// ---------------------------------------------------------------------------
// TreeDecoder on GB300 — round 17.
// GEMM2 on tensor cores via portable mma.sync.m16n8k16 (bf16-split, 3 terms,
// fp32 accum). Round-16 fix: FT smem row stride 72 -> 80 bytes so cp.async
// 16B destinations are aligned. GEMM1 + prelim = 135.7us FFMA2 champion.
// ---------------------------------------------------------------------------

#define NSPLIT 10
#define N_PRE    184            // 40 Fcomb + 128 Q2 + 16 Q01
#define N_MAIN   1024
#define N_BLOCKS (N_PRE + N_MAIN)
#define N_RED    64

typedef unsigned long long ull;

__device__ __forceinline__ ull dup2(float x) {
    ull r; unsigned u = __float_as_uint(x);
    asm("mov.b64 %0, {%1, %1};" : "=l"(r) : "r"(u));
    return r;
}
__device__ __forceinline__ void fma2(ull& d, ull a, ull b) {
    asm("fma.rn.f32x2 %0, %1, %2, %0;" : "+l"(d) : "l"(a), "l"(b));
}
__device__ __forceinline__ float lo32(ull v) { return __uint_as_float((unsigned)v); }
__device__ __forceinline__ float hi32(ull v) { return __uint_as_float((unsigned)(v >> 32)); }
__device__ __forceinline__ unsigned smem_u32(const void* p) {
    unsigned a;
    asm("{ .reg .u64 t; cvta.to.shared.u64 t, %1; cvt.u32.u64 %0, t; }" : "=r"(a) : "l"(p));
    return a;
}
__device__ __forceinline__ void cp16_cg(unsigned s, const void* g) {
    asm volatile("cp.async.cg.shared.global [%0], [%1], 16;" :: "r"(s), "l"(g));
}
#define CP_COMMIT()  asm volatile("cp.async.commit_group;")
#define CP_WAIT0()   asm volatile("cp.async.wait_group 0;")

// mma.sync m16n8k16 row.col f32.bf16.bf16.f32 (portable HMMA path)
#define MMA_BF16(d, a, b0, b1) \
    asm volatile("mma.sync.aligned.m16n8k16.row.col.f32.bf16.bf16.f32 " \
        "{%0,%1,%2,%3}, {%4,%5,%6,%7}, {%8,%9}, {%0,%1,%2,%3};" \
        : "+f"((d)[0]), "+f"((d)[1]), "+f"((d)[2]), "+f"((d)[3]) \
        : "r"((a)[0]), "r"((a)[1]), "r"((a)[2]), "r"((a)[3]), "r"(b0), "r"(b1))

// Device scratch (zero-init counters; last block re-zeroes per launch)
__device__ float    g_Fbias[128];
__device__ float    g_Fpart[NSPLIT * 16384];
__device__ float    g_Fbpart[NSPLIT * 128];
__device__ unsigned g_FTh[128 * 64];   // FcombT[c][m] hi, bf16x2 words over m
__device__ unsigned g_FTl[128 * 64];   // lo part
__device__ float    g_A2[32 * 128 * 128];
__device__ float    g_Q01[32 * 16 * 128];
__device__ int      g_cnt_f, g_cnt_r, g_cnt_pre, g_cnt_done;

__device__ __forceinline__ void block_signal(int* cnt) {
    __threadfence();
    __syncthreads();
    if (threadIdx.x == 0) atomicAdd(cnt, 1);
}
__device__ __forceinline__ void block_wait(int* cnt, int target) {
    if (threadIdx.x == 0) {
        while (atomicAdd(cnt, 0) < target) __nanosleep(128);
        __threadfence();
    }
    __syncthreads();
}

// ---------------------------------------------------------------------------
// smem (main branch), byte offsets:
//   T3      [0, 16384)        floats [32][128]          (persists)
//   As      [16384, 32768)    floats [32][128]          (GEMM1)
//   Wb      [32768, 81920)    floats [2][6144]          (GEMM1)
//   -- GEMM2 overlays (after GEMM1 completes) --
//   C1h     [16384, 33280)    bf16 [64][stride 132] (66 words/row)
//   C1l     [33280, 50176)
//   FT st0  [50176, 70656)    hi [128][stride 80B] + lo at +10240
//   FT st1  [70656, 91136)
// total 91136 B -> 2 CTAs/SM.
// ---------------------------------------------------------------------------
__global__ __launch_bounds__(256, 2)
void fused_kernel(const float* __restrict__ tree0,
                  const float* __restrict__ tree1,
                  const float* __restrict__ tree2,
                  const float* __restrict__ tree3,
                  const float* __restrict__ Uw0, const float* __restrict__ Ub0,
                  const float* __restrict__ Uw1, const float* __restrict__ Ub1,
                  const float* __restrict__ Uw2, const float* __restrict__ Ub2,
                  const float* __restrict__ Uw3, const float* __restrict__ Ub3,
                  const float* __restrict__ W_up,
                  const float* __restrict__ Fw0, const float* __restrict__ Fb0,
                  const float* __restrict__ Fw1, const float* __restrict__ Fb1,
                  const float* __restrict__ b_bias,
                  float* __restrict__ out) {
    extern __shared__ float sh[];
    const int tid = threadIdx.x;
    const int bx  = blockIdx.x;
    const int ty  = tid >> 5;
    const int tx  = tid & 31;

    if (bx < 40) {
        // ================= Fcomb split-K partial =================
        float* As = sh;          // [32][128]
        float* Bs = sh + 4096;   // [32][128]
        const int s  = bx >> 2;
        const int rt = bx & 3;

        for (int i4 = tid; i4 < 1024; i4 += 256) {
            int r = i4 >> 5, k4 = (i4 & 31) << 2;
            *(float4*)&As[r * 128 + k4] =
                *(const float4*)&Fw0[(rt * 32 + r) * 1280 + s * 128 + k4];
        }
        float acc[4][4] = {};
        float bacc = 0.f;
        for (int kb = 0; kb < 128; kb += 32) {
            __syncthreads();
            for (int i4 = tid; i4 < 1024; i4 += 256) {
                int j = i4 >> 5, o4 = (i4 & 31) << 2;
                *(float4*)&Bs[j * 128 + o4] =
                    *(const float4*)&Fw1[(s * 128 + kb + j) * 128 + o4];
            }
            __syncthreads();
            #pragma unroll 8
            for (int j = 0; j < 32; ++j) {
                float w[4];
                #pragma unroll
                for (int c = 0; c < 4; ++c) w[c] = Bs[j * 128 + tx + 32 * c];
                #pragma unroll
                for (int r = 0; r < 4; ++r) {
                    float a = As[(ty * 4 + r) * 128 + kb + j];
                    #pragma unroll
                    for (int c = 0; c < 4; ++c) acc[r][c] = fmaf(a, w[c], acc[r][c]);
                }
            }
            if (rt == 0 && tid < 128) {
                #pragma unroll 8
                for (int j = 0; j < 32; ++j)
                    bacc = fmaf(Fb0[s * 128 + kb + j], Bs[j * 128 + tid], bacc);
            }
        }
        #pragma unroll
        for (int r = 0; r < 4; ++r)
            #pragma unroll
            for (int c = 0; c < 4; ++c)
                g_Fpart[s * 16384 + (rt * 32 + ty * 4 + r) * 128 + tx + 32 * c] = acc[r][c];
        if (rt == 0 && tid < 128) g_Fbpart[s * 128 + tid] = bacc;
        block_signal(&g_cnt_f);

    } else if (bx < 168) {
        // ================= Q2 GEMM =================
        float* x2s = sh;
        float* Bs  = sh + 4096;
        const int r0 = (bx - 40) * 32;

        for (int i4 = tid; i4 < 1024; i4 += 256) {
            int lr = i4 >> 5, k4 = (i4 & 31) << 2;
            *(float4*)&x2s[lr * 128 + k4] =
                *(const float4*)&tree2[(r0 + lr) * 128 + k4];
        }
        float acc[4][4] = {};
        for (int kb = 0; kb < 128; kb += 32) {
            __syncthreads();
            for (int i4 = tid; i4 < 1024; i4 += 256) {
                int j = i4 >> 5, o4 = (i4 & 31) << 2;
                *(float4*)&Bs[j * 128 + o4] =
                    *(const float4*)&Uw2[(kb + j) * 128 + o4];
            }
            __syncthreads();
            #pragma unroll 8
            for (int j = 0; j < 32; ++j) {
                float w[4];
                #pragma unroll
                for (int c = 0; c < 4; ++c) w[c] = Bs[j * 128 + tx + 32 * c];
                #pragma unroll
                for (int r = 0; r < 4; ++r) {
                    float a = x2s[(ty * 4 + r) * 128 + kb + j];
                    #pragma unroll
                    for (int c = 0; c < 4; ++c) acc[r][c] = fmaf(a, w[c], acc[r][c]);
                }
            }
        }
        #pragma unroll
        for (int r = 0; r < 4; ++r)
            #pragma unroll
            for (int c = 0; c < 4; ++c)
                g_A2[(r0 + ty * 4 + r) * 128 + tx + 32 * c] = acc[r][c];
        block_signal(&g_cnt_pre);

    } else if (bx < N_PRE) {
        // ================= Q01 =================
        float* t1s   = sh;            // [32][32]
        float* w1s   = sh + 1024;     // [32][128]
        float* w0s   = sh + 5120;     // [32][128]
        float* t0s   = sh + 9216;     // [2][32]
        float* q0buf = sh + 9280;     // [2][128]
        const int q  = bx - 168;
        const int g0 = q * 32;

        float acc[4][4] = {};
        float q0a = 0.f;
        const int q0row = tid >> 7;
        const int q0col = tid & 127;

        for (int kb = 0; kb < 128; kb += 32) {
            __syncthreads();
            {
                int row = tid >> 3, k4 = (tid & 7) << 2;
                *(float4*)&t1s[row * 32 + k4] =
                    *(const float4*)&tree1[(g0 + row) * 128 + kb + k4];
            }
            for (int i4 = tid; i4 < 1024; i4 += 256) {
                int j = i4 >> 5, o4 = (i4 & 31) << 2;
                *(float4*)&w1s[j * 128 + o4] =
                    *(const float4*)&Uw1[(kb + j) * 128 + o4];
                *(float4*)&w0s[j * 128 + o4] =
                    *(const float4*)&Uw0[(kb + j) * 128 + o4];
            }
            if (tid < 16) {
                int row = tid >> 3, k4 = (tid & 7) << 2;
                *(float4*)&t0s[row * 32 + k4] =
                    *(const float4*)&tree0[(q * 2 + row) * 128 + kb + k4];
            }
            __syncthreads();
            #pragma unroll 8
            for (int j = 0; j < 32; ++j) {
                float w[4];
                #pragma unroll
                for (int c = 0; c < 4; ++c) w[c] = w1s[j * 128 + tx + 32 * c];
                #pragma unroll
                for (int r = 0; r < 4; ++r) {
                    float a = t1s[(ty * 4 + r) * 32 + j];
                    #pragma unroll
                    for (int c = 0; c < 4; ++c) acc[r][c] = fmaf(a, w[c], acc[r][c]);
                }
            }
            #pragma unroll 8
            for (int j = 0; j < 32; ++j)
                q0a = fmaf(t0s[q0row * 32 + j], w0s[j * 128 + q0col], q0a);
        }
        __syncthreads();
        q0buf[tid] = q0a;
        __syncthreads();
        #pragma unroll
        for (int r = 0; r < 4; ++r) {
            int row = ty * 4 + r;
            int bl  = row >> 4;
            #pragma unroll
            for (int c = 0; c < 4; ++c) {
                int col = tx + 32 * c;
                g_Q01[(g0 + row) * 128 + col] =
                    acc[r][c] + q0buf[bl * 128 + col]
                    + Ub0[col] + Ub1[col] + Ub2[col];
            }
        }
        block_signal(&g_cnt_pre);

    } else {
        // ================= main: FFMA2 GEMM1 + mma.sync GEMM2 =================
        float* T3 = sh;                 // [32][128]
        float* As = sh + 4096;          // [32][128] (GEMM1 only)
        float* Wb = sh + 8192;          // [2][6144] (GEMM1 only)
        char*  shb = (char*)sh;
        const int n = bx - N_PRE;
        const unsigned wb_u32 = smem_u32(Wb);

        // GEMM1 fill: 6 x 16B per thread per stage over [16 rows][96 float4]
        const char* g1src[6];
        int         g1step[6];
        unsigned    g1soff[6];
        #pragma unroll
        for (int q = 0; q < 6; ++q) {
            int g = tid + 256 * q;
            int kk = g / 96, c4 = g - kk * 96;
            if (c4 < 64) {
                g1src[q]  = (const char*)(W_up + ((size_t)n * 128 + kk) * 256 + c4 * 4);
                g1step[q] = 16 * 256 * 4;
            } else {
                g1src[q]  = (const char*)(Uw3 + kk * 128 + (c4 - 64) * 4);
                g1step[q] = 16 * 128 * 4;
            }
            g1soff[q] = (unsigned)(kk * 384 + c4 * 4) * 4;
        }
        #pragma unroll
        for (int q = 0; q < 6; ++q) cp16_cg(wb_u32 + g1soff[q], g1src[q]);
        CP_COMMIT();

        for (int idx = tid; idx < 1024; idx += 256) {
            int bb = idx >> 5, i4 = (idx & 31) << 2;
            *(float4*)&As[bb * 128 + i4] =
                *(const float4*)&tree3[((size_t)bb * 1024 + n) * 128 + i4];
        }

        const int tn = tid & 31;
        const int tm = tid >> 5;
        ull acc[4][6] = {};

        // ---- GEMM1: 8 stages of K=16 (champion) ----
        for (int it = 0; it < 8; ++it) {
            CP_WAIT0();
            __syncthreads();
            if (it < 7) {
                unsigned dst = wb_u32 + (unsigned)(((it + 1) & 1) * 6144 * 4);
                #pragma unroll
                for (int q = 0; q < 6; ++q) {
                    g1src[q] += g1step[q];
                    cp16_cg(dst + g1soff[q], g1src[q]);
                }
                CP_COMMIT();
            }
            const float* buf = Wb + (it & 1) * 6144;
            const int k0 = it * 16;
            #pragma unroll
            for (int kk = 0; kk < 16; ++kk) {
                ull ad[4];
                #pragma unroll
                for (int r = 0; r < 4; ++r)
                    ad[r] = dup2(As[(tm * 4 + r) * 128 + k0 + kk]);
                ull w[6];
                #pragma unroll
                for (int j = 0; j < 6; ++j)
                    w[j] = *(const ull*)&buf[kk * 384 + tn * 2 + 64 * j];
                #pragma unroll
                for (int r = 0; r < 4; ++r)
                    #pragma unroll
                    for (int j = 0; j < 6; ++j)
                        fma2(acc[r][j], ad[r], w[j]);
            }
        }
        __syncthreads();   // all As/Wb reads done; safe to overlay

        // ---- Store T3 + bf16-split C1 into padded smem tiles ----
        char* c1h = shb + 16384;
        char* c1l = shb + 33280;
        #pragma unroll
        for (int r = 0; r < 4; ++r) {
            int b = tm * 4 + r;
            #pragma unroll
            for (int j = 4; j < 6; ++j)
                *(ull*)&T3[b * 128 + tn * 2 + 64 * j - 256] = acc[r][j];
            #pragma unroll
            for (int j = 0; j < 4; ++j) {
                int c0 = tn * 2 + 64 * j;
                int m  = c0 & 127, dd = c0 >> 7;
                int row = b * 2 + dd;
                float v0 = lo32(acc[r][j]), v1 = hi32(acc[r][j]);
                __nv_bfloat16 h0 = __float2bfloat16(v0), h1 = __float2bfloat16(v1);
                __nv_bfloat16 l0 = __float2bfloat16(v0 - __bfloat162float(h0));
                __nv_bfloat16 l1 = __float2bfloat16(v1 - __bfloat162float(h1));
                __nv_bfloat162 ph = __halves2bfloat162(h0, h1);
                __nv_bfloat162 pl = __halves2bfloat162(l0, l1);
                unsigned off = (unsigned)(row * 66 + (m >> 1)) * 4;
                *(unsigned*)(c1h + off) = *(unsigned*)&ph;
                *(unsigned*)(c1l + off) = *(unsigned*)&pl;
            }
        }

        // ---- Fcomb reduce -> bf16-split FcombT (blocks 184..247) ----
        if (n < N_RED) {
            block_wait(&g_cnt_f, 40);
            int idx = n * 256 + tid;
            if (idx < 8192) {
                int cc = idx & 127;
                int m0 = (idx >> 7) << 1;
                float a0 = 0.f, a1 = 0.f;
                #pragma unroll
                for (int s = 0; s < NSPLIT; ++s) {
                    a0 += g_Fpart[s * 16384 + m0 * 128 + cc];
                    a1 += g_Fpart[s * 16384 + (m0 + 1) * 128 + cc];
                }
                __nv_bfloat16 h0 = __float2bfloat16(a0), h1 = __float2bfloat16(a1);
                __nv_bfloat16 l0 = __float2bfloat16(a0 - __bfloat162float(h0));
                __nv_bfloat16 l1 = __float2bfloat16(a1 - __bfloat162float(h1));
                __nv_bfloat162 ph = __halves2bfloat162(h0, h1);
                __nv_bfloat162 pl = __halves2bfloat162(l0, l1);
                g_FTh[cc * 64 + (m0 >> 1)] = *(unsigned*)&ph;
                g_FTl[cc * 64 + (m0 >> 1)] = *(unsigned*)&pl;
            }
            if (n == 0 && tid < 128) {
                float b = Fb1[tid];
                #pragma unroll
                for (int s = 0; s < NSPLIT; ++s) b += g_Fbpart[s * 128 + tid];
                g_Fbias[tid] = b;
            }
            block_signal(&g_cnt_r);
        }
        block_wait(&g_cnt_r, N_RED);   // FT ready in global; C1h/C1l published

        // ---- FT pipeline: k-chunks of 32, double-buffered ----
        // stage s base = 50176 + s*20480: hi [128 rows][80 B], lo at +10240.
        // Row r holds 16 words (32 bf16 k-values) + 4 words pad.
        #define FT_FILL(kc, sbuf) do {                                         \
            unsigned base_ = smem_u32(shb + 50176 + (sbuf) * 20480);           \
            _Pragma("unroll")                                                  \
            for (int q_ = 0; q_ < 2; ++q_) {                                   \
                int i_ = tid + 256 * q_;                                       \
                int nr_ = i_ >> 2, gg_ = i_ & 3;                               \
                cp16_cg(base_ + (unsigned)(nr_ * 80 + gg_ * 16),               \
                        (const char*)g_FTh + nr_ * 256 + (kc) * 64 + gg_ * 16);\
                cp16_cg(base_ + 10240u + (unsigned)(nr_ * 80 + gg_ * 16),      \
                        (const char*)g_FTl + nr_ * 256 + (kc) * 64 + gg_ * 16);\
            }                                                                  \
            CP_COMMIT();                                                       \
        } while (0)

        FT_FILL(0, 0);

        const int wm = ty >> 1;       // 0..3 -> D rows wm*16..+15
        const int wn = ty & 1;        // 0..1 -> D cols wn*64..+63
        const int lg = tx >> 2;       // 0..7
        const int lt = tx & 3;        // 0..3
        float dacc[8][4] = {};

        for (int kc = 0; kc < 4; ++kc) {
            CP_WAIT0();
            __syncthreads();
            if (kc < 3) FT_FILL(kc + 1, (kc + 1) & 1);
            char* fth = shb + 50176 + (kc & 1) * 20480;
            char* ftl = fth + 10240;
            #pragma unroll
            for (int ks = 0; ks < 2; ++ks) {
                const int k0 = kc * 32 + ks * 16;
                const int w0 = (k0 >> 1) + lt;          // a word index
                unsigned ah[4], al[4];
                {
                    int r0 = wm * 16 + lg, r1 = r0 + 8;
                    ah[0] = *(const unsigned*)(c1h + (r0 * 66 + w0) * 4);
                    ah[1] = *(const unsigned*)(c1h + (r1 * 66 + w0) * 4);
                    ah[2] = *(const unsigned*)(c1h + (r0 * 66 + w0 + 4) * 4);
                    ah[3] = *(const unsigned*)(c1h + (r1 * 66 + w0 + 4) * 4);
                    al[0] = *(const unsigned*)(c1l + (r0 * 66 + w0) * 4);
                    al[1] = *(const unsigned*)(c1l + (r1 * 66 + w0) * 4);
                    al[2] = *(const unsigned*)(c1l + (r0 * 66 + w0 + 4) * 4);
                    al[3] = *(const unsigned*)(c1l + (r1 * 66 + w0 + 4) * 4);
                }
                #pragma unroll
                for (int nt = 0; nt < 8; ++nt) {
                    int nn = wn * 64 + nt * 8 + lg;     // B col (output c)
                    int bw = ks * 8 + lt;               // b word within chunk
                    unsigned bh0 = *(const unsigned*)(fth + (nn * 20 + bw) * 4);
                    unsigned bh1 = *(const unsigned*)(fth + (nn * 20 + bw + 4) * 4);
                    unsigned bl0 = *(const unsigned*)(ftl + (nn * 20 + bw) * 4);
                    unsigned bl1 = *(const unsigned*)(ftl + (nn * 20 + bw + 4) * 4);
                    MMA_BF16(dacc[nt], ah, bh0, bh1);   // Ch * Fh
                    MMA_BF16(dacc[nt], ah, bl0, bl1);   // Ch * Fl
                    MMA_BF16(dacc[nt], al, bh0, bh1);   // Cl * Fh
                }
            }
        }

        block_wait(&g_cnt_pre, 144);

        // ---- Epilogue: fragment D -> out ----
        const int j2 = n >> 3;
        const int j1 = n >> 6;
        #pragma unroll
        for (int nt = 0; nt < 8; ++nt) {
            int cc = wn * 64 + nt * 8 + lt * 2;
            float2 ub = *(const float2*)&Ub3[cc];
            float2 fb = *(const float2*)&g_Fbias[cc];
            #pragma unroll
            for (int hh = 0; hh < 2; ++hh) {
                int rowg = wm * 16 + lg + hh * 8;
                int b  = rowg >> 1;
                int dd = rowg & 1;
                float2 t3  = *(const float2*)&T3[b * 128 + cc];
                float2 a2v = *(const float2*)&g_A2[(b * 128 + j2) * 128 + cc];
                float2 q01 = *(const float2*)&g_Q01[(b * 16 + j1) * 128 + cc];
                float2 bbv = *(const float2*)&b_bias[(2 * n + dd) * 128 + cc];
                float vx = dacc[nt][hh * 2 + 0] + t3.x + ub.x + fb.x + a2v.x + q01.x + bbv.x;
                float vy = dacc[nt][hh * 2 + 1] + t3.y + ub.y + fb.y + a2v.y + q01.y + bbv.y;
                float2 o;
                o.x = (vx >= 0.f) ? vx : 0.2f * vx;
                o.y = (vy >= 0.f) ? vy : 0.2f * vy;
                *(float2*)&out[((size_t)b * 2048 + 2 * n + dd) * 128 + cc] = o;
            }
        }
    }

    // ---- Per-launch counter cleanup ----
    __syncthreads();
    if (tid == 0) {
        __threadfence();
        int d = atomicAdd(&g_cnt_done, 1);
        if (d == N_BLOCKS - 1) {
            g_cnt_f = 0; g_cnt_r = 0; g_cnt_pre = 0;
            __threadfence();
            g_cnt_done = 0;
        }
    }
}

// ---------------------------------------------------------------------------
extern "C" void kernel_launch(void* const* d_in, const int* in_sizes, int n_in,
                              void* d_out, int out_size) {
    const float* tree0  = (const float*)d_in[0];
    const float* tree1  = (const float*)d_in[1];
    const float* tree2  = (const float*)d_in[2];
    const float* tree3  = (const float*)d_in[3];
    const float* Uw0    = (const float*)d_in[4];
    const float* Ub0    = (const float*)d_in[5];
    const float* Uw1    = (const float*)d_in[6];
    const float* Ub1    = (const float*)d_in[7];
    const float* Uw2    = (const float*)d_in[8];
    const float* Ub2    = (const float*)d_in[9];
    const float* Uw3    = (const float*)d_in[10];
    const float* Ub3    = (const float*)d_in[11];
    const float* W_up   = (const float*)d_in[12];
    const float* Fw0    = (const float*)d_in[13];
    const float* Fb0    = (const float*)d_in[14];
    const float* Fw1    = (const float*)d_in[15];
    const float* Fb1    = (const float*)d_in[16];
    const float* b_bias = (const float*)d_in[17];
    float* out = (float*)d_out;

    cudaFuncSetAttribute(fused_kernel,
                         cudaFuncAttributeMaxDynamicSharedMemorySize, 91136);

    fused_kernel<<<N_BLOCKS, 256, 91136>>>(
        tree0, tree1, tree2, tree3,
        Uw0, Ub0, Uw1, Ub1, Uw2, Ub2, Uw3, Ub3,
        W_up, Fw0, Fb0, Fw1, Fb1, b_bias, out);
}